// round 5
// baseline (speedup 1.0000x reference)
#include <cuda_runtime.h>
#include <cuda_fp16.h>

// Problem constants
#define BATCH    128
#define SEQT     256
#define HID      128
#define WIN      16
#define NSTEP    3840          // (256-16)*16 chained LSTM steps
#define NTHREADS 512           // 16 warps; warp w owns hidden units [8w, 8w+8)

// HW tanh (MUFU.TANH) and sigmoid via tanh
__device__ __forceinline__ float tanh_fast(float x) {
    float y; asm("tanh.approx.f32 %0, %1;" : "=f"(y) : "f"(x)); return y;
}
__device__ __forceinline__ float sigm_fast(float x) {
    return __fmaf_rn(0.5f, tanh_fast(0.5f * x), 0.5f);
}
__device__ __forceinline__ unsigned pack_h2(float lo, float hi) {
    __half2 h = __floats2half2_rn(lo, hi);
    return *reinterpret_cast<unsigned*>(&h);
}
// m16n8k16 row.col f16*f16 -> f32 accumulate (warp-level HMMA)
__device__ __forceinline__ void mma16816(float* c, const unsigned* a, unsigned b0, unsigned b1) {
    asm volatile(
        "mma.sync.aligned.m16n8k16.row.col.f32.f16.f16.f32 "
        "{%0,%1,%2,%3},{%4,%5,%6,%7},{%8,%9},{%0,%1,%2,%3};\n"
        : "+f"(c[0]), "+f"(c[1]), "+f"(c[2]), "+f"(c[3])
        : "r"(a[0]), "r"(a[1]), "r"(a[2]), "r"(a[3]), "r"(b0), "r"(b1));
}

__global__ void __launch_bounds__(NTHREADS, 1)
lstm_mma3_kernel(const float* __restrict__ x,
                 const float* __restrict__ W_ih,
                 const float* __restrict__ W_hh,
                 const float* __restrict__ b_ih,
                 const float* __restrict__ b_hh,
                 const float* __restrict__ fc_W,
                 const float* __restrict__ fc_b,
                 float* __restrict__ out)
{
    __shared__ float sx[SEQT];
    // Double-buffered h: sh[p][0..127] = h_hi, sh[p][128..255] = h_lo
    __shared__ __align__(16) __half sh[2][2 * HID];
    __shared__ float sred[16];

    const int tid = threadIdx.x;
    const int b   = blockIdx.x;
    const int w   = tid >> 5;          // warp 0..15
    const int l   = tid & 31;
    const int gid = l >> 2;            // 0..7 (frag row group / B column)
    const int tg  = l & 3;             // 0..3 (frag column pair / B k-pair)
    const int j   = 8 * w + gid;       // hidden unit owned by lane 4*gid (tg==0)

    // ---------------- Prologue: A fragments, gate-interleaved rows ---------
    // tile0: frag rows gid -> W_hh row j (gate i), rows gid+8 -> 128+j (gate f)
    // tile1: frag rows gid -> 256+j (gate g),      rows gid+8 -> 384+j (gate o)
    unsigned Afrag[2][8][4];
    {
        const float* ri = W_hh + (size_t)j * HID;
        const float* rf = W_hh + (size_t)(HID + j) * HID;
        const float* rg = W_hh + (size_t)(2 * HID + j) * HID;
        const float* ro = W_hh + (size_t)(3 * HID + j) * HID;
#pragma unroll
        for (int kk = 0; kk < 8; ++kk) {
            const int k0 = 16 * kk + 2 * tg;
            Afrag[0][kk][0] = pack_h2(ri[k0],     ri[k0 + 1]);
            Afrag[0][kk][1] = pack_h2(rf[k0],     rf[k0 + 1]);
            Afrag[0][kk][2] = pack_h2(ri[k0 + 8], ri[k0 + 9]);
            Afrag[0][kk][3] = pack_h2(rf[k0 + 8], rf[k0 + 9]);
            Afrag[1][kk][0] = pack_h2(rg[k0],     rg[k0 + 1]);
            Afrag[1][kk][1] = pack_h2(ro[k0],     ro[k0 + 1]);
            Afrag[1][kk][2] = pack_h2(rg[k0 + 8], rg[k0 + 9]);
            Afrag[1][kk][3] = pack_h2(ro[k0 + 8], ro[k0 + 9]);
        }
    }

    // Per-lane gate biases / W_ih for unit j (meaningful at tg==0)
    const float bias_i = b_ih[j]           + b_hh[j];
    const float bias_f = b_ih[HID + j]     + b_hh[HID + j];
    const float bias_g = b_ih[2 * HID + j] + b_hh[2 * HID + j];
    const float bias_o = b_ih[3 * HID + j] + b_hh[3 * HID + j];
    const float wih_i  = W_ih[j];
    const float wih_f  = W_ih[HID + j];
    const float wih_g  = W_ih[2 * HID + j];
    const float wih_o  = W_ih[3 * HID + j];
    const float fcw    = fc_W[j];
    const float fcb    = fc_b[0];
    float c_state = 0.f;

    if (tid < 2 * HID) { sh[0][tid] = __float2half_rn(0.f); }   // h0 = 0 (buf 0)
    if (tid < SEQT) sx[tid] = x[(size_t)b * SEQT + tid];
    if (tid < WIN)  out[(size_t)b * SEQT + tid] = x[(size_t)b * SEQT + tid];
    __syncthreads();

    // B-column content: col 1 (gid==1) reads h_lo; every other column reads
    // h_hi (cols 2..7 are garbage but never consumed -> valid dummy loads).
    const int rd_off = (gid == 1) ? HID : 0;

    // ---------------- 3840 chained steps, one barrier per step -------------
    for (int s = 0; s < NSTEP; ++s) {
        const __half* bp  = sh[s & 1] + rd_off;          // read buffer
        __half*       shw = sh[(s & 1) ^ 1];             // write buffer
        const float xt = sx[(s >> 4) + (s & (WIN - 1))];

        // cA: kk 0..3, cB: kk 4..7 (two half-depth chains per tile)
        float cA[2][4], cB[2][4];
        cA[0][0] = __fmaf_rn(xt, wih_i, bias_i);  cA[0][1] = 0.f;
        cA[0][2] = __fmaf_rn(xt, wih_f, bias_f);  cA[0][3] = 0.f;
        cA[1][0] = __fmaf_rn(xt, wih_g, bias_g);  cA[1][1] = 0.f;
        cA[1][2] = __fmaf_rn(xt, wih_o, bias_o);  cA[1][3] = 0.f;
#pragma unroll
        for (int t = 0; t < 2; ++t) { cB[t][0]=0.f; cB[t][1]=0.f; cB[t][2]=0.f; cB[t][3]=0.f; }

#pragma unroll
        for (int kk = 0; kk < 4; ++kk) {
            unsigned b0 = *(const unsigned*)(bp + 16 * kk + 2 * tg);
            unsigned b1 = *(const unsigned*)(bp + 16 * kk + 8 + 2 * tg);
            mma16816(cA[0], Afrag[0][kk], b0, b1);
            mma16816(cA[1], Afrag[1][kk], b0, b1);
        }
#pragma unroll
        for (int kk = 4; kk < 8; ++kk) {
            unsigned b0 = *(const unsigned*)(bp + 16 * kk + 2 * tg);
            unsigned b1 = *(const unsigned*)(bp + 16 * kk + 8 + 2 * tg);
            mma16816(cB[0], Afrag[0][kk], b0, b1);
            mma16816(cB[1], Afrag[1][kk], b0, b1);
        }

        // At tg==0: c[0]=col0 (W.h_hi), c[1]=col1 (W.h_lo); rows gid / gid+8.
        const float gi = (cA[0][0] + cB[0][0]) + (cA[0][1] + cB[0][1]);
        const float gf = (cA[0][2] + cB[0][2]) + (cA[0][3] + cB[0][3]);
        const float gg = (cA[1][0] + cB[1][0]) + (cA[1][1] + cB[1][1]);
        const float go = (cA[1][2] + cB[1][2]) + (cA[1][3] + cB[1][3]);

        c_state = sigm_fast(gf) * c_state + sigm_fast(gi) * tanh_fast(gg);
        const float h = sigm_fast(go) * tanh_fast(c_state);

        const __half hh = __float2half_rn(h);
        const __half hl = __float2half_rn(h - __half2float(hh));
        if (tg == 0) {                       // unit j's owner writes h
            shw[j]       = hh;
            shw[HID + j] = hl;
        }

        const bool tap = ((s & (WIN - 1)) == (WIN - 1));
        if (tap) {
            float p = (tg == 0) ? fcw * h : 0.f;
            p += __shfl_down_sync(0xffffffffu, p, 16);
            p += __shfl_down_sync(0xffffffffu, p, 8);
            p += __shfl_down_sync(0xffffffffu, p, 4);
            if (l == 0) sred[w] = p;
        }

        __syncthreads();                     // h + sred visible to everyone

        if (tap && tid == 0) {
            float v = fcb;
#pragma unroll
            for (int i = 0; i < 16; ++i) v += sred[i];
            out[(size_t)b * SEQT + WIN + (s >> 4)] = (v >= 0.f) ? v : 0.3f * v;
        }
    }
}

extern "C" void kernel_launch(void* const* d_in, const int* in_sizes, int n_in,
                              void* d_out, int out_size)
{
    const float* x    = (const float*)d_in[0];
    const float* W_ih = (const float*)d_in[1];
    const float* W_hh = (const float*)d_in[2];
    const float* b_ih = (const float*)d_in[3];
    const float* b_hh = (const float*)d_in[4];
    const float* fc_W = (const float*)d_in[5];
    const float* fc_b = (const float*)d_in[6];

    lstm_mma3_kernel<<<BATCH, NTHREADS>>>(
        x, W_ih, W_hh, b_ih, b_hh, fc_W, fc_b, (float*)d_out);
}

// round 6
// speedup vs baseline: 1.6045x; 1.6045x over previous
#include <cuda_runtime.h>
#include <cuda_fp16.h>

// Problem constants
#define BATCH    128
#define SEQT     256
#define HID      128
#define WIN      16
#define NSTEP    3840          // (256-16)*16 chained LSTM steps
#define NROWS    512           // 4*HID gate rows
#define NTHREADS 512           // 16 warps; warp w owns gate rows [32w, 32w+32)

// HW tanh (MUFU.TANH) and sigmoid via tanh
__device__ __forceinline__ float tanh_fast(float x) {
    float y; asm("tanh.approx.f32 %0, %1;" : "=f"(y) : "f"(x)); return y;
}
__device__ __forceinline__ float sigm_fast(float x) {
    return __fmaf_rn(0.5f, tanh_fast(0.5f * x), 0.5f);
}
__device__ __forceinline__ unsigned pack_h2(float lo, float hi) {
    __half2 h = __floats2half2_rn(lo, hi);
    return *reinterpret_cast<unsigned*>(&h);
}
// m16n8k16 row.col f16*f16 -> f32 accumulate (warp-level HMMA)
__device__ __forceinline__ void mma16816(float* c, const unsigned* a, unsigned b0, unsigned b1) {
    asm volatile(
        "mma.sync.aligned.m16n8k16.row.col.f32.f16.f16.f32 "
        "{%0,%1,%2,%3},{%4,%5,%6,%7},{%8,%9},{%0,%1,%2,%3};\n"
        : "+f"(c[0]), "+f"(c[1]), "+f"(c[2]), "+f"(c[3])
        : "r"(a[0]), "r"(a[1]), "r"(a[2]), "r"(a[3]), "r"(b0), "r"(b1));
}

__global__ void __launch_bounds__(NTHREADS, 1)
lstm_mma4_kernel(const float* __restrict__ x,
                 const float* __restrict__ W_ih,
                 const float* __restrict__ W_hh,
                 const float* __restrict__ b_ih,
                 const float* __restrict__ b_hh,
                 const float* __restrict__ fc_W,
                 const float* __restrict__ fc_b,
                 float* __restrict__ out)
{
    __shared__ float sx[SEQT];
    __shared__ float sg[NROWS];                       // gate totals (hi+lo summed)
    __shared__ __align__(16) __half sh_hi[HID];       // h (fp16 high)
    __shared__ __align__(16) __half sh_lo[HID];       // h residual (fp16)
    __shared__ float sred[4];

    const int tid = threadIdx.x;
    const int b   = blockIdx.x;
    const int w   = tid >> 5;          // warp 0..15
    const int l   = tid & 31;
    const int gid = l >> 2;            // 0..7  (frag row group / B column)
    const int tg  = l & 3;             // 0..3

    // ---------------- Prologue: A fragments (W_hh fp16, resident in RF) ----
    unsigned Afrag[2][8][4];
#pragma unroll
    for (int t = 0; t < 2; ++t) {
        const int R = 32 * w + 16 * t;
        const float* r0 = W_hh + (R + gid)     * HID;
        const float* r8 = W_hh + (R + gid + 8) * HID;
#pragma unroll
        for (int kk = 0; kk < 8; ++kk) {
            const int k0 = 16 * kk + 2 * tg;
            Afrag[t][kk][0] = pack_h2(r0[k0],     r0[k0 + 1]);
            Afrag[t][kk][1] = pack_h2(r8[k0],     r8[k0 + 1]);
            Afrag[t][kk][2] = pack_h2(r0[k0 + 8], r0[k0 + 9]);
            Afrag[t][kk][3] = pack_h2(r8[k0 + 8], r8[k0 + 9]);
        }
    }

    // Per-lane bias / W_ih for rows (gid, gid+8) of each tile (used at tg==0)
    float biasr[2][2], wihr[2][2];
#pragma unroll
    for (int t = 0; t < 2; ++t) {
        const int R = 32 * w + 16 * t;
        biasr[t][0] = b_ih[R + gid]     + b_hh[R + gid];
        biasr[t][1] = b_ih[R + gid + 8] + b_hh[R + gid + 8];
        wihr[t][0]  = W_ih[R + gid];
        wihr[t][1]  = W_ih[R + gid + 8];
    }

    const float fcw = (tid < HID) ? fc_W[tid] : 0.f;
    const float fcb = fc_b[0];
    float c_state = 0.f;

    if (tid < HID) {
        sh_hi[tid] = __float2half_rn(0.f);
        sh_lo[tid] = __float2half_rn(0.f);
    }
    if (tid < SEQT) sx[tid] = x[b * SEQT + tid];
    if (tid < WIN)  out[b * SEQT + tid] = x[b * SEQT + tid];
    __syncthreads();

    // B-column content: col 1 (gid==1) = h_lo; all other columns read h_hi
    // (cols 2..7 are valid dummy loads, their D columns are never consumed).
    const __half* bp = (gid == 1) ? sh_lo : sh_hi;

    // ---------------- 3840 chained steps -----------------------------------
    for (int s = 0; s < NSTEP; ++s) {
        const float xt = sx[(s >> 4) + (s & (WIN - 1))];

        // Two half-depth chains per tile: cA (kk 0..3) + cB (kk 4..7).
        // Bias + x*W_ih folded into D col 0 (c[0]/c[2] of tg==0 lanes).
        float cA[2][4], cB[2][4];
#pragma unroll
        for (int t = 0; t < 2; ++t) {
            if (tg == 0) {
                cA[t][0] = __fmaf_rn(xt, wihr[t][0], biasr[t][0]);
                cA[t][2] = __fmaf_rn(xt, wihr[t][1], biasr[t][1]);
            } else {
                cA[t][0] = 0.f; cA[t][2] = 0.f;
            }
            cA[t][1] = 0.f; cA[t][3] = 0.f;
            cB[t][0] = 0.f; cB[t][1] = 0.f; cB[t][2] = 0.f; cB[t][3] = 0.f;
        }

#pragma unroll
        for (int kk = 0; kk < 4; ++kk) {
            unsigned b0 = *(const unsigned*)(bp + 16 * kk + 2 * tg);
            unsigned b1 = *(const unsigned*)(bp + 16 * kk + 8 + 2 * tg);
            mma16816(cA[0], Afrag[0][kk], b0, b1);
            mma16816(cA[1], Afrag[1][kk], b0, b1);
        }
#pragma unroll
        for (int kk = 4; kk < 8; ++kk) {
            unsigned b0 = *(const unsigned*)(bp + 16 * kk + 2 * tg);
            unsigned b1 = *(const unsigned*)(bp + 16 * kk + 8 + 2 * tg);
            mma16816(cB[0], Afrag[0][kk], b0, b1);
            mma16816(cB[1], Afrag[1][kk], b0, b1);
        }

        // tg==0 lanes: c[0]=col0(W.h_hi), c[1]=col1(W.h_lo) for row gid;
        //              c[2],c[3] same for row gid+8. Sum in-register, 1 array.
        if (tg == 0) {
#pragma unroll
            for (int t = 0; t < 2; ++t) {
                const int R = 32 * w + 16 * t;
                sg[R + gid]     = (cA[t][0] + cB[t][0]) + (cA[t][1] + cB[t][1]);
                sg[R + gid + 8] = (cA[t][2] + cB[t][2]) + (cA[t][3] + cB[t][3]);
            }
        }
        __syncthreads();

        // Gate combine: hidden unit tid (warps 0..3)
        if (tid < HID) {
            const float gi = sg[tid];
            const float gf = sg[tid + HID];
            const float gg = sg[tid + 2 * HID];
            const float go = sg[tid + 3 * HID];
            c_state = sigm_fast(gf) * c_state + sigm_fast(gi) * tanh_fast(gg);
            const float h = sigm_fast(go) * tanh_fast(c_state);

            const __half hh = __float2half_rn(h);
            sh_hi[tid] = hh;
            sh_lo[tid] = __float2half_rn(h - __half2float(hh));

            if ((s & (WIN - 1)) == (WIN - 1)) {            // fc tap at t=15
                float p = fcw * h;
                p += __shfl_down_sync(0xffffffffu, p, 16);
                p += __shfl_down_sync(0xffffffffu, p, 8);
                p += __shfl_down_sync(0xffffffffu, p, 4);
                p += __shfl_down_sync(0xffffffffu, p, 2);
                p += __shfl_down_sync(0xffffffffu, p, 1);
                if ((l & 31) == 0) sred[tid >> 5] = p;
            }
        }
        __syncthreads();

        if (((s & (WIN - 1)) == (WIN - 1)) && tid == 0) {
            float v = sred[0] + sred[1] + sred[2] + sred[3] + fcb;
            out[b * SEQT + WIN + (s >> 4)] = (v >= 0.f) ? v : 0.3f * v;
        }
    }
}

extern "C" void kernel_launch(void* const* d_in, const int* in_sizes, int n_in,
                              void* d_out, int out_size)
{
    const float* x    = (const float*)d_in[0];
    const float* W_ih = (const float*)d_in[1];
    const float* W_hh = (const float*)d_in[2];
    const float* b_ih = (const float*)d_in[3];
    const float* b_hh = (const float*)d_in[4];
    const float* fc_W = (const float*)d_in[5];
    const float* fc_b = (const float*)d_in[6];

    lstm_mma4_kernel<<<BATCH, NTHREADS>>>(
        x, W_ih, W_hh, b_ih, b_hh, fc_W, fc_b, (float*)d_out);
}

// round 7
// speedup vs baseline: 1.6829x; 1.0489x over previous
#include <cuda_runtime.h>
#include <cuda_fp16.h>

// Problem constants
#define BATCH    128
#define SEQT     256
#define HID      128
#define WIN      16
#define NSTEP    3840          // (256-16)*16 chained LSTM steps
#define NROWS    512           // 4*HID gate rows
#define NTHREADS 512           // 16 warps; warp w owns gate rows [32w, 32w+32)

// Named barriers (1: sg ready -> combine; 2: h ready -> everyone)
#define BAR_ARRIVE(id) asm volatile("bar.arrive %0, %1;" :: "r"(id), "r"(NTHREADS) : "memory")
#define BAR_SYNC(id)   asm volatile("bar.sync %0, %1;"   :: "r"(id), "r"(NTHREADS) : "memory")

// HW tanh (MUFU.TANH) and sigmoid via tanh
__device__ __forceinline__ float tanh_fast(float x) {
    float y; asm("tanh.approx.f32 %0, %1;" : "=f"(y) : "f"(x)); return y;
}
__device__ __forceinline__ float sigm_fast(float x) {
    return __fmaf_rn(0.5f, tanh_fast(0.5f * x), 0.5f);
}
__device__ __forceinline__ unsigned pack_h2(float lo, float hi) {
    __half2 h = __floats2half2_rn(lo, hi);
    return *reinterpret_cast<unsigned*>(&h);
}
// m16n8k16 row.col f16*f16 -> f32 accumulate (warp-level HMMA)
__device__ __forceinline__ void mma16816(float* c, const unsigned* a, unsigned b0, unsigned b1) {
    asm volatile(
        "mma.sync.aligned.m16n8k16.row.col.f32.f16.f16.f32 "
        "{%0,%1,%2,%3},{%4,%5,%6,%7},{%8,%9},{%0,%1,%2,%3};\n"
        : "+f"(c[0]), "+f"(c[1]), "+f"(c[2]), "+f"(c[3])
        : "r"(a[0]), "r"(a[1]), "r"(a[2]), "r"(a[3]), "r"(b0), "r"(b1));
}

__global__ void __launch_bounds__(NTHREADS, 1)
lstm_mma5_kernel(const float* __restrict__ x,
                 const float* __restrict__ W_ih,
                 const float* __restrict__ W_hh,
                 const float* __restrict__ b_ih,
                 const float* __restrict__ b_hh,
                 const float* __restrict__ fc_W,
                 const float* __restrict__ fc_b,
                 float* __restrict__ out)
{
    __shared__ float sx[SEQT];
    __shared__ float sg[NROWS];                       // gate totals (hi+lo summed)
    __shared__ __align__(16) __half sh_hi[HID];       // h (fp16 high)
    __shared__ __align__(16) __half sh_lo[HID];       // h residual (fp16)
    __shared__ float sred[4];

    const int tid = threadIdx.x;
    const int b   = blockIdx.x;
    const int w   = tid >> 5;          // warp 0..15
    const int l   = tid & 31;
    const int gid = l >> 2;            // 0..7  (frag row group / B column)
    const int tg  = l & 3;             // 0..3
    const bool combiner = (w >= 12);   // warps 12-15 run the cell combine
    const int  cu = tid - 384;         // combiner's hidden unit (0..127)

    // ---------------- Prologue: A fragments (W_hh fp16, resident in RF) ----
    unsigned Afrag[2][8][4];
#pragma unroll
    for (int t = 0; t < 2; ++t) {
        const int R = 32 * w + 16 * t;
        const float* r0 = W_hh + (R + gid)     * HID;
        const float* r8 = W_hh + (R + gid + 8) * HID;
#pragma unroll
        for (int kk = 0; kk < 8; ++kk) {
            const int k0 = 16 * kk + 2 * tg;
            Afrag[t][kk][0] = pack_h2(r0[k0],     r0[k0 + 1]);
            Afrag[t][kk][1] = pack_h2(r8[k0],     r8[k0 + 1]);
            Afrag[t][kk][2] = pack_h2(r0[k0 + 8], r0[k0 + 9]);
            Afrag[t][kk][3] = pack_h2(r8[k0 + 8], r8[k0 + 9]);
        }
    }

    // Per-lane bias / W_ih for rows (gid, gid+8) of each tile (used at tg==0)
    float biasr[2][2], wihr[2][2];
#pragma unroll
    for (int t = 0; t < 2; ++t) {
        const int R = 32 * w + 16 * t;
        biasr[t][0] = b_ih[R + gid]     + b_hh[R + gid];
        biasr[t][1] = b_ih[R + gid + 8] + b_hh[R + gid + 8];
        wihr[t][0]  = W_ih[R + gid];
        wihr[t][1]  = W_ih[R + gid + 8];
    }

    const float fcw = combiner ? fc_W[cu] : 0.f;
    const float fcb = fc_b[0];
    float c_state = 0.f;

    if (tid < HID) {
        sh_hi[tid] = __float2half_rn(0.f);
        sh_lo[tid] = __float2half_rn(0.f);
    }
    if (tid < SEQT) sx[tid] = x[b * SEQT + tid];
    if (tid < WIN)  out[b * SEQT + tid] = x[b * SEQT + tid];
    __syncthreads();

    // B-column content: col 1 (gid==1) = h_lo; all other columns read h_hi
    // (cols 2..7 are valid dummy loads, their D columns are never consumed).
    const __half* bp = (gid == 1) ? sh_lo : sh_hi;

    // ---------------- 3840 chained steps -----------------------------------
    for (int s = 0; s < NSTEP; ++s) {
        const float xt = sx[(s >> 4) + (s & (WIN - 1))];

        // Two half-depth chains per tile: cA (kk 0..3) + cB (kk 4..7).
        // Bias + x*W_ih folded into D col 0 (c[0]/c[2] of tg==0 lanes).
        float cA[2][4], cB[2][4];
#pragma unroll
        for (int t = 0; t < 2; ++t) {
            if (tg == 0) {
                cA[t][0] = __fmaf_rn(xt, wihr[t][0], biasr[t][0]);
                cA[t][2] = __fmaf_rn(xt, wihr[t][1], biasr[t][1]);
            } else {
                cA[t][0] = 0.f; cA[t][2] = 0.f;
            }
            cA[t][1] = 0.f; cA[t][3] = 0.f;
            cB[t][0] = 0.f; cB[t][1] = 0.f; cB[t][2] = 0.f; cB[t][3] = 0.f;
        }

#pragma unroll
        for (int kk = 0; kk < 4; ++kk) {
            unsigned b0 = *(const unsigned*)(bp + 16 * kk + 2 * tg);
            unsigned b1 = *(const unsigned*)(bp + 16 * kk + 8 + 2 * tg);
            mma16816(cA[0], Afrag[0][kk], b0, b1);
            mma16816(cA[1], Afrag[1][kk], b0, b1);
        }
#pragma unroll
        for (int kk = 4; kk < 8; ++kk) {
            unsigned b0 = *(const unsigned*)(bp + 16 * kk + 2 * tg);
            unsigned b1 = *(const unsigned*)(bp + 16 * kk + 8 + 2 * tg);
            mma16816(cB[0], Afrag[0][kk], b0, b1);
            mma16816(cB[1], Afrag[1][kk], b0, b1);
        }

        // tg==0 lanes: c[0]=col0(W.h_hi), c[1]=col1(W.h_lo) for row gid;
        //              c[2],c[3] same for row gid+8. Sum in-register, 1 array.
        if (tg == 0) {
#pragma unroll
            for (int t = 0; t < 2; ++t) {
                const int R = 32 * w + 16 * t;
                sg[R + gid]     = (cA[t][0] + cB[t][0]) + (cA[t][1] + cB[t][1]);
                sg[R + gid + 8] = (cA[t][2] + cB[t][2]) + (cA[t][3] + cB[t][3]);
            }
        }

        if (!combiner) {
            // Producers: post sg, then block only once (until h is ready).
            BAR_ARRIVE(1);
            BAR_SYNC(2);
        } else {
            // Combiners (warps 12-15, highest arbiter priority): wait for sg.
            BAR_SYNC(1);

            const float gi = sg[cu];
            const float gf = sg[cu + HID];
            const float gg = sg[cu + 2 * HID];
            const float go = sg[cu + 3 * HID];
            c_state = sigm_fast(gf) * c_state + sigm_fast(gi) * tanh_fast(gg);
            const float h = sigm_fast(go) * tanh_fast(c_state);

            const __half hh = __float2half_rn(h);
            sh_hi[cu] = hh;
            sh_lo[cu] = __float2half_rn(h - __half2float(hh));

            if ((s & (WIN - 1)) == (WIN - 1)) {            // fc tap at t=15
                float p = fcw * h;
                p += __shfl_down_sync(0xffffffffu, p, 16);
                p += __shfl_down_sync(0xffffffffu, p, 8);
                p += __shfl_down_sync(0xffffffffu, p, 4);
                p += __shfl_down_sync(0xffffffffu, p, 2);
                p += __shfl_down_sync(0xffffffffu, p, 1);
                if (l == 0) sred[w - 12] = p;
            }
            BAR_SYNC(2);

            if (((s & (WIN - 1)) == (WIN - 1)) && tid == 384) {
                float v = sred[0] + sred[1] + sred[2] + sred[3] + fcb;
                out[b * SEQT + WIN + (s >> 4)] = (v >= 0.f) ? v : 0.3f * v;
            }
        }
    }
}

extern "C" void kernel_launch(void* const* d_in, const int* in_sizes, int n_in,
                              void* d_out, int out_size)
{
    const float* x    = (const float*)d_in[0];
    const float* W_ih = (const float*)d_in[1];
    const float* W_hh = (const float*)d_in[2];
    const float* b_ih = (const float*)d_in[3];
    const float* b_hh = (const float*)d_in[4];
    const float* fc_W = (const float*)d_in[5];
    const float* fc_b = (const float*)d_in[6];

    lstm_mma5_kernel<<<BATCH, NTHREADS>>>(
        x, W_ih, W_hh, b_ih, b_hh, fc_W, fc_b, (float*)d_out);
}